// round 2
// baseline (speedup 1.0000x reference)
#include <cuda_runtime.h>
#include <stdint.h>

#define NPTS 256
#define DIM  256
#define KNN  16
#define NB   128        // 2 rows per block; 128 < 148 SMs -> single-wave residency guaranteed
#define EPSV 1e-12f

// Persistent device scratch (no allocations allowed)
__device__ float g_YnT[DIM * NPTS];   // transposed normalized yi: [c][j]
__device__ float g_rn[NPTS];          // ||yn_j||^2 (exactly s/(s+eps))
__device__ float g_part[NPTS];        // per-row loss partials
__device__ unsigned int g_bar  = 0;   // barrier arrival counter (self-resetting)
__device__ unsigned int g_rel  = 0;   // barrier release epoch (monotonic)
__device__ unsigned int g_done = 0;   // last-block counter (self-resetting)

__device__ __forceinline__ float block_sum_256(float v, float* sh) {
    int lane = threadIdx.x & 31;
    int w    = threadIdx.x >> 5;
    #pragma unroll
    for (int o = 16; o; o >>= 1) v += __shfl_down_sync(0xffffffffu, v, o);
    if (lane == 0) sh[w] = v;
    __syncthreads();
    float r;
    if (w == 0) {
        r = (lane < 8) ? sh[lane] : 0.0f;
        #pragma unroll
        for (int o = 4; o; o >>= 1) r += __shfl_down_sync(0xffffffffu, r, o);
        if (lane == 0) sh[0] = r;
    }
    __syncthreads();
    r = sh[0];
    __syncthreads();
    return r;
}

__global__ __launch_bounds__(256, 1)
void k_fused(const float* __restrict__ yi, const float* __restrict__ yit,
             float* __restrict__ out) {
    __shared__ float4 s4[DIM];          // (yn_r0, ytn_r0, yn_r1, ytn_r1) per channel c
    __shared__ float  shred[8];
    __shared__ float  sh_d1[2][NPTS];
    __shared__ float  sh_d2[2][NPTS];
    __shared__ float  sh_sc[6];         // rn0, rn1, rt0, rt1, dself0, dself1
    __shared__ unsigned s_last;

    const int t  = threadIdx.x;
    const int b  = blockIdx.x;
    const int r0 = 2 * b, r1 = r0 + 1;

    // epoch read MUST precede this block's barrier arrival (it does)
    unsigned epoch = 0;
    if (t == 0) epoch = *((volatile unsigned*)&g_rel);

    // ---------------- Phase A: normalize rows r0, r1 ----------------
    float a0 = yi [r0 * DIM + t];
    float c0 = yit[r0 * DIM + t];
    float a1 = yi [r1 * DIM + t];
    float c1 = yit[r1 * DIM + t];

    float sa0 = block_sum_256(a0 * a0, shred);
    float sc0 = block_sum_256(c0 * c0, shred);
    float sa1 = block_sum_256(a1 * a1, shred);
    float sc1 = block_sum_256(c1 * c1, shred);

    float ia0 = 1.0f / sqrtf(sa0 + EPSV), ic0 = 1.0f / sqrtf(sc0 + EPSV);
    float ia1 = 1.0f / sqrtf(sa1 + EPSV), ic1 = 1.0f / sqrtf(sc1 + EPSV);
    float an0 = a0 * ia0, cn0 = c0 * ic0;
    float an1 = a1 * ia1, cn1 = c1 * ic1;

    g_YnT[t * NPTS + r0] = an0;         // transposed store (scattered, tiny)
    g_YnT[t * NPTS + r1] = an1;
    s4[t] = make_float4(an0, cn0, an1, cn1);

    float d0 = an0 - cn0, d1x = an1 - cn1;
    float sd0 = block_sum_256(d0 * d0,  shred);
    float sd1 = block_sum_256(d1x * d1x, shred);

    if (t == 0) {
        float rn0 = sa0 * ia0 * ia0, rn1 = sa1 * ia1 * ia1;
        sh_sc[0] = rn0;                 sh_sc[1] = rn1;
        sh_sc[2] = sc0 * ic0 * ic0;     sh_sc[3] = sc1 * ic1 * ic1;
        sh_sc[4] = 0.5f * sqrtf(sd0 + EPSV);
        sh_sc[5] = 0.5f * sqrtf(sd1 + EPSV);
        g_rn[r0] = rn0;                 g_rn[r1] = rn1;
    }

    // ---------------- software grid barrier ----------------
    __threadfence();
    __syncthreads();
    if (t == 0) {
        unsigned arrived = atomicAdd(&g_bar, 1);
        if (arrived == NB - 1) {
            *((volatile unsigned*)&g_bar) = 0;   // reset for next graph replay
            __threadfence();
            atomicAdd(&g_rel, 1);
        } else {
            while (*((volatile unsigned*)&g_rel) == epoch) __nanosleep(32);
        }
        __threadfence();
    }
    __syncthreads();

    // ---------------- Phase B: 4 dot products per thread (column j = t) ----------------
    float accn0 = 0.f, acct0 = 0.f, accn1 = 0.f, acct1 = 0.f;
    #pragma unroll 8
    for (int c = 0; c < DIM; c++) {
        float v = g_YnT[c * NPTS + t];  // coalesced across threads
        float4 s = s4[c];               // LDS.128 broadcast
        accn0 = fmaf(s.x, v, accn0);
        acct0 = fmaf(s.y, v, acct0);
        accn1 = fmaf(s.z, v, accn1);
        acct1 = fmaf(s.w, v, acct1);
    }
    float rnj = *((volatile float*)&g_rn[t]);
    float rn0 = sh_sc[0], rn1 = sh_sc[1], rt0 = sh_sc[2], rt1 = sh_sc[3];
    sh_d1[0][t] = 0.5f * sqrtf(fmaxf(rn0 + rnj - 2.f * accn0, 0.f) + EPSV);
    sh_d2[0][t] = 0.5f * sqrtf(fmaxf(rt0 + rnj - 2.f * acct0, 0.f) + EPSV);
    sh_d1[1][t] = 0.5f * sqrtf(fmaxf(rn1 + rnj - 2.f * accn1, 0.f) + EPSV);
    sh_d2[1][t] = 0.5f * sqrtf(fmaxf(rt1 + rnj - 2.f * acct1, 0.f) + EPSV);
    __syncthreads();

    // ---------------- Selection: warp w in {0,1} handles row r0+w, no block barriers ----------------
    const int w = t >> 5, l = t & 31;
    if (w < 2) {
        const int   row = r0 + w;
        const float* D1 = sh_d1[w];
        const float* D2 = sh_d2[w];
        unsigned long long k[8];
        #pragma unroll
        for (int m = 0; m < 8; m++) {
            int j = m * 32 + l;
            k[m] = ((unsigned long long)__float_as_uint(D1[j]) << 32) | (unsigned)j;
            if (j == row) k[m] = ~0ull;   // exclude self (always the row min)
        }
        float acc = 0.f, first = 0.f;
        for (int it = 0; it < KNN; it++) {
            unsigned long long best = k[0];
            #pragma unroll
            for (int m = 1; m < 8; m++) if (k[m] < best) best = k[m];
            #pragma unroll
            for (int o = 16; o; o >>= 1) {
                unsigned long long u = __shfl_down_sync(0xffffffffu, best, o);
                if (u < best) best = u;
            }
            best = __shfl_sync(0xffffffffu, best, 0);
            int   jw  = (int)(best & 0xffffffffull);
            float d1w = __uint_as_float((unsigned)(best >> 32));
            if (it == 0) first = d1w;     // 1st real neighbor = reference's second_nn
            float diff = d1w - D2[jw];    // broadcast LDS
            acc = fmaf(diff, diff, acc);
            if (l == (jw & 31)) k[jw >> 5] = ~0ull;   // remove winner
        }
        if (l == 0) {
            float ds = sh_sc[4 + w];
            g_part[row] = (acc - (float)KNN * 0.0025f)
                        + fmaxf(ds + 0.6f - first, 0.f);
        }
    }

    // ---------------- last block does the deterministic final reduce ----------------
    __threadfence();
    __syncthreads();
    if (t == 0) s_last = atomicAdd(&g_done, 1);
    __syncthreads();
    if (s_last == NB - 1) {
        float v = *((volatile float*)&g_part[t]);
        float s = block_sum_256(v, shred);
        if (t == 0) {
            out[0] = s;
            *((volatile unsigned*)&g_done) = 0;   // reset for next replay
        }
    }
}

extern "C" void kernel_launch(void* const* d_in, const int* in_sizes, int n_in,
                              void* d_out, int out_size) {
    const float* yi  = (const float*)d_in[0];
    const float* yit = (const float*)d_in[1];
    float* out = (float*)d_out;
    k_fused<<<NB, 256>>>(yi, yit, out);
}